// round 2
// baseline (speedup 1.0000x reference)
#include <cuda_runtime.h>
#include <math.h>

#define B_ 4
#define N1_ 16384
#define N2_ 4096
#define C1_ 128
#define C2_ 256
#define O1_ 256   // MLP layer1 out
#define O2_ 128   // MLP layer2 out
#define ROWS_TOT (B_ * N1_)   // 65536

// ---------------- scratch (device globals; no allocation allowed) ----------
__device__ int   g_idx[B_ * N1_ * 3];
__device__ float g_w  [B_ * N1_ * 3];
__device__ float g_Zt [B_ * N2_ * O1_];          // [b][m][o]  (n-major)
__device__ float g_y1 [B_ * N1_ * O1_];          // [b][n][o]  pre-BN layer1
__device__ float g_y2 [B_ * N1_ * O2_];          // [b][n][o]  pre-BN layer2
__device__ float g_s1[O1_], g_q1[O1_], g_scale1[O1_], g_shift1[O1_];
__device__ float g_s2[O2_], g_q2[O2_], g_scale2[O2_], g_shift2[O2_];

// ---------------- 1) 3-NN + inverse-distance weights -----------------------
__global__ void knn_kernel(const float* __restrict__ xyz1,
                           const float* __restrict__ xyz2) {
    const int b = blockIdx.y;
    const int n = blockIdx.x * 128 + threadIdx.x;
    __shared__ float sx[1024], sy[1024], sz[1024];

    const float* X1 = xyz1 + (size_t)b * 3 * N1_;
    const float* X2 = xyz2 + (size_t)b * 3 * N2_;
    const float qx = X1[n];
    const float qy = X1[N1_ + n];
    const float qz = X1[2 * N1_ + n];

    float d0 = 3.4e38f, d1 = 3.4e38f, d2 = 3.4e38f;
    int   i0 = 0, i1 = 0, i2 = 0;

    for (int t = 0; t < N2_ / 1024; t++) {
        __syncthreads();
        for (int j = threadIdx.x; j < 1024; j += 128) {
            sx[j] = X2[t * 1024 + j];
            sy[j] = X2[N2_ + t * 1024 + j];
            sz[j] = X2[2 * N2_ + t * 1024 + j];
        }
        __syncthreads();
        #pragma unroll 4
        for (int j = 0; j < 1024; j++) {
            float dx = qx - sx[j], dy = qy - sy[j], dz = qz - sz[j];
            float d = fmaf(dx, dx, fmaf(dy, dy, dz * dz));
            if (d < d2) {
                int jj = t * 1024 + j;
                if (d < d1) {
                    d2 = d1; i2 = i1;
                    if (d < d0) { d1 = d0; i1 = i0; d0 = d; i0 = jj; }
                    else        { d1 = d;  i1 = jj; }
                } else { d2 = d; i2 = jj; }
            }
        }
    }
    d0 = fmaxf(d0, 1e-10f); d1 = fmaxf(d1, 1e-10f); d2 = fmaxf(d2, 1e-10f);
    float w0 = 1.0f / d0, w1 = 1.0f / d1, w2 = 1.0f / d2;
    float inv = 1.0f / (w0 + w1 + w2);
    size_t base = ((size_t)b * N1_ + n) * 3;
    g_idx[base + 0] = i0; g_idx[base + 1] = i1; g_idx[base + 2] = i2;
    g_w[base + 0] = w0 * inv; g_w[base + 1] = w1 * inv; g_w[base + 2] = w2 * inv;
}

// ---------------- 2) Zt[b][m][o] = sum_c W1[o][128+c] * p2[b][c][m] --------
// grid (N2/128, O1/128, B), block 256
__global__ void __launch_bounds__(256) zt_gemm(const float* __restrict__ p2,
                                               const float* __restrict__ W1) {
    const int b = blockIdx.z, ot = blockIdx.y, mt = blockIdx.x;
    __shared__ float As[16][128];    // [k][m]
    __shared__ float Bs[128][17];    // [o][k]
    const int tid = threadIdx.x, tx = tid & 31, ty = tid >> 5;
    float acc[16][4] = {};

    const float* Ab = p2 + (size_t)b * C2_ * N2_ + mt * 128;
    const float* Bb = W1 + (size_t)(ot * 128) * 384 + 128;

    for (int kc = 0; kc < C2_ / 16; kc++) {
        #pragma unroll
        for (int r = 0; r < 8; r++) {
            int e = tid + r * 256; int k = e >> 7, m = e & 127;
            As[k][m] = Ab[(size_t)(kc * 16 + k) * N2_ + m];
        }
        #pragma unroll
        for (int r = 0; r < 8; r++) {
            int e = tid + r * 256; int o = e >> 4, k = e & 15;
            Bs[o][k] = Bb[(size_t)o * 384 + kc * 16 + k];
        }
        __syncthreads();
        #pragma unroll
        for (int k = 0; k < 16; k++) {
            float bv[4];
            #pragma unroll
            for (int j = 0; j < 4; j++) bv[j] = Bs[tx + 32 * j][k];
            #pragma unroll
            for (int i = 0; i < 16; i++) {
                float a = As[k][ty + 8 * i];
                #pragma unroll
                for (int j = 0; j < 4; j++) acc[i][j] = fmaf(a, bv[j], acc[i][j]);
            }
        }
        __syncthreads();
    }
    float* Cb = g_Zt + ((size_t)b * N2_ + mt * 128) * O1_ + ot * 128;
    #pragma unroll
    for (int i = 0; i < 16; i++)
        #pragma unroll
        for (int j = 0; j < 4; j++)
            Cb[(size_t)(ty + 8 * i) * O1_ + tx + 32 * j] = acc[i][j];
}

// ---------------- 3) zero stats ---------------------------------------------
__global__ void zero_stats() {
    int t = threadIdx.x;
    if (t < O1_) { g_s1[t] = 0.f; g_q1[t] = 0.f; }
    if (t < O2_) { g_s2[t] = 0.f; g_q2[t] = 0.f; }
}

// ---------------- 4) GEMM1: y1[b][n][o] = b1 + W1a·p1 + Σ w·Zt[idx] --------
// fused: per-block BN1 partial sums -> global atomics
// grid (N1/128, O1/128, B), block 256
__global__ void __launch_bounds__(256) gemm1(const float* __restrict__ p1,
                                             const float* __restrict__ W1,
                                             const float* __restrict__ b1) {
    const int b = blockIdx.z, ot = blockIdx.y, nt = blockIdx.x;
    __shared__ float As[16][128];    // [k][n]
    __shared__ float Bs[128][17];    // [o][k]
    __shared__ int   sidx[128][3];
    __shared__ float sw[128][3];
    __shared__ float red_s[128], red_q[128];
    const int tid = threadIdx.x, tx = tid & 31, ty = tid >> 5;
    float acc[16][4] = {};

    if (tid < 128) {
        size_t base = ((size_t)b * N1_ + nt * 128 + tid) * 3;
        #pragma unroll
        for (int k = 0; k < 3; k++) { sidx[tid][k] = g_idx[base + k]; sw[tid][k] = g_w[base + k]; }
        red_s[tid] = 0.f; red_q[tid] = 0.f;
    }

    const float* Ab = p1 + (size_t)b * C1_ * N1_ + nt * 128;
    const float* Bb = W1 + (size_t)(ot * 128) * 384;

    for (int kc = 0; kc < C1_ / 16; kc++) {
        #pragma unroll
        for (int r = 0; r < 8; r++) {
            int e = tid + r * 256; int k = e >> 7, m = e & 127;
            As[k][m] = Ab[(size_t)(kc * 16 + k) * N1_ + m];
        }
        #pragma unroll
        for (int r = 0; r < 8; r++) {
            int e = tid + r * 256; int o = e >> 4, k = e & 15;
            Bs[o][k] = Bb[(size_t)o * 384 + kc * 16 + k];
        }
        __syncthreads();
        #pragma unroll
        for (int k = 0; k < 16; k++) {
            float bv[4];
            #pragma unroll
            for (int j = 0; j < 4; j++) bv[j] = Bs[tx + 32 * j][k];
            #pragma unroll
            for (int i = 0; i < 16; i++) {
                float a = As[k][ty + 8 * i];
                #pragma unroll
                for (int j = 0; j < 4; j++) acc[i][j] = fmaf(a, bv[j], acc[i][j]);
            }
        }
        __syncthreads();
    }

    // epilogue: bias + 3-NN gather from Zt
    float bb[4];
    #pragma unroll
    for (int j = 0; j < 4; j++) bb[j] = b1[ot * 128 + tx + 32 * j];
    const float* Ztb = g_Zt + (size_t)b * N2_ * O1_ + ot * 128;
    #pragma unroll
    for (int i = 0; i < 16; i++) {
        int nl = ty + 8 * i;
        #pragma unroll
        for (int j = 0; j < 4; j++) acc[i][j] += bb[j];
        #pragma unroll
        for (int k = 0; k < 3; k++) {
            int m = sidx[nl][k];
            float wv = sw[nl][k];
            const float* z = Ztb + (size_t)m * O1_;
            #pragma unroll
            for (int j = 0; j < 4; j++) acc[i][j] = fmaf(wv, z[tx + 32 * j], acc[i][j]);
        }
    }

    float* Cb = g_y1 + ((size_t)b * N1_ + nt * 128) * O1_ + ot * 128;
    #pragma unroll
    for (int i = 0; i < 16; i++)
        #pragma unroll
        for (int j = 0; j < 4; j++)
            Cb[(size_t)(ty + 8 * i) * O1_ + tx + 32 * j] = acc[i][j];

    // fused BN1 partial stats: column = local (tx + 32j), 8 ty-partials each
    float ps[4] = {}, pq[4] = {};
    #pragma unroll
    for (int i = 0; i < 16; i++)
        #pragma unroll
        for (int j = 0; j < 4; j++) { ps[j] += acc[i][j]; pq[j] = fmaf(acc[i][j], acc[i][j], pq[j]); }
    #pragma unroll
    for (int j = 0; j < 4; j++) {
        atomicAdd(&red_s[tx + 32 * j], ps[j]);
        atomicAdd(&red_q[tx + 32 * j], pq[j]);
    }
    __syncthreads();
    if (tid < 128) {
        atomicAdd(&g_s1[ot * 128 + tid], red_s[tid]);
        atomicAdd(&g_q1[ot * 128 + tid], red_q[tid]);
    }
}

__global__ void fin_stats1(const float* __restrict__ g, const float* __restrict__ be) {
    int c = threadIdx.x;
    if (c < O1_) {
        const float invN = 1.0f / (float)ROWS_TOT;
        float m = g_s1[c] * invN;
        float v = g_q1[c] * invN - m * m;
        float sc = g[c] * rsqrtf(v + 1e-5f);
        g_scale1[c] = sc;
        g_shift1[c] = be[c] - m * sc;
    }
}
__global__ void fin_stats2(const float* __restrict__ g, const float* __restrict__ be) {
    int c = threadIdx.x;
    if (c < O2_) {
        const float invN = 1.0f / (float)ROWS_TOT;
        float m = g_s2[c] * invN;
        float v = g_q2[c] * invN - m * m;
        float sc = g[c] * rsqrtf(v + 1e-5f);
        g_scale2[c] = sc;
        g_shift2[c] = be[c] - m * sc;
    }
}

// ---------------- 6) GEMM2: y2[b][n][o] = b2 + W2 · relu(aff1(y1)) ---------
// fused: per-block BN2 partial sums -> global atomics
// grid (N1/128, 1, B), block 256
__global__ void __launch_bounds__(256) gemm2(const float* __restrict__ W2,
                                             const float* __restrict__ b2) {
    const int b = blockIdx.z, nt = blockIdx.x;
    __shared__ float As[128][17];    // [n][k]
    __shared__ float Bs[128][17];    // [o][k]
    __shared__ float ssc[O1_], ssh[O1_];
    __shared__ float red_s[128], red_q[128];
    const int tid = threadIdx.x, tx = tid & 31, ty = tid >> 5;
    float acc[16][4] = {};

    ssc[tid] = g_scale1[tid];
    ssh[tid] = g_shift1[tid];
    if (tid < 128) { red_s[tid] = 0.f; red_q[tid] = 0.f; }
    __syncthreads();

    const float* Ab = g_y1 + ((size_t)b * N1_ + nt * 128) * O1_;

    for (int kc = 0; kc < O1_ / 16; kc++) {
        #pragma unroll
        for (int r = 0; r < 8; r++) {
            int e = tid + r * 256; int n = e >> 4, k = e & 15;
            int c = kc * 16 + k;
            float v = Ab[(size_t)n * O1_ + c];
            As[n][k] = fmaxf(fmaf(ssc[c], v, ssh[c]), 0.f);
        }
        #pragma unroll
        for (int r = 0; r < 8; r++) {
            int e = tid + r * 256; int o = e >> 4, k = e & 15;
            Bs[o][k] = W2[(size_t)o * O1_ + kc * 16 + k];
        }
        __syncthreads();
        #pragma unroll
        for (int k = 0; k < 16; k++) {
            float bv[4];
            #pragma unroll
            for (int j = 0; j < 4; j++) bv[j] = Bs[tx + 32 * j][k];
            #pragma unroll
            for (int i = 0; i < 16; i++) {
                float a = As[ty + 8 * i][k];
                #pragma unroll
                for (int j = 0; j < 4; j++) acc[i][j] = fmaf(a, bv[j], acc[i][j]);
            }
        }
        __syncthreads();
    }

    float bb[4];
    #pragma unroll
    for (int j = 0; j < 4; j++) bb[j] = b2[tx + 32 * j];
    #pragma unroll
    for (int i = 0; i < 16; i++)
        #pragma unroll
        for (int j = 0; j < 4; j++) acc[i][j] += bb[j];

    float* Cb = g_y2 + ((size_t)b * N1_ + nt * 128) * O2_;
    #pragma unroll
    for (int i = 0; i < 16; i++)
        #pragma unroll
        for (int j = 0; j < 4; j++)
            Cb[(size_t)(ty + 8 * i) * O2_ + tx + 32 * j] = acc[i][j];

    // fused BN2 partial stats
    float ps[4] = {}, pq[4] = {};
    #pragma unroll
    for (int i = 0; i < 16; i++)
        #pragma unroll
        for (int j = 0; j < 4; j++) { ps[j] += acc[i][j]; pq[j] = fmaf(acc[i][j], acc[i][j], pq[j]); }
    #pragma unroll
    for (int j = 0; j < 4; j++) {
        atomicAdd(&red_s[tx + 32 * j], ps[j]);
        atomicAdd(&red_q[tx + 32 * j], pq[j]);
    }
    __syncthreads();
    if (tid < 128) {
        atomicAdd(&g_s2[tid], red_s[tid]);
        atomicAdd(&g_q2[tid], red_q[tid]);
    }
}

// ---------------- 7) finalize: BN2 affine + relu + transpose to (B,C,N) ----
// grid (N1/32, O2/32, B), block (32,8)
__global__ void transpose_out(float* __restrict__ out) {
    __shared__ float t[32][33];
    const int b = blockIdx.z;
    const int o0 = blockIdx.y * 32, n0 = blockIdx.x * 32;
    const int tx = threadIdx.x;
    for (int r = threadIdx.y; r < 32; r += 8) {
        int n = n0 + r, o = o0 + tx;
        float v = g_y2[((size_t)b * N1_ + n) * O2_ + o];
        v = fmaxf(fmaf(g_scale2[o], v, g_shift2[o]), 0.f);
        t[r][tx] = v;
    }
    __syncthreads();
    for (int r = threadIdx.y; r < 32; r += 8) {
        int o = o0 + r, n = n0 + tx;
        out[((size_t)b * O2_ + o) * N1_ + n] = t[tx][r];
    }
}

// ---------------- launch ----------------------------------------------------
extern "C" void kernel_launch(void* const* d_in, const int* in_sizes, int n_in,
                              void* d_out, int out_size) {
    const float* xyz1 = (const float*)d_in[0];
    const float* xyz2 = (const float*)d_in[1];
    const float* p1   = (const float*)d_in[2];
    const float* p2   = (const float*)d_in[3];
    const float* W1   = (const float*)d_in[4];
    const float* b1   = (const float*)d_in[5];
    const float* g1   = (const float*)d_in[6];
    const float* be1  = (const float*)d_in[7];
    const float* W2   = (const float*)d_in[8];
    const float* b2   = (const float*)d_in[9];
    const float* g2   = (const float*)d_in[10];
    const float* be2  = (const float*)d_in[11];
    float* out = (float*)d_out;

    knn_kernel<<<dim3(N1_ / 128, B_), 128>>>(xyz1, xyz2);
    zt_gemm<<<dim3(N2_ / 128, O1_ / 128, B_), 256>>>(p2, W1);
    zero_stats<<<1, 256>>>();
    gemm1<<<dim3(N1_ / 128, O1_ / 128, B_), 256>>>(p1, W1, b1);
    fin_stats1<<<1, O1_>>>(g1, be1);
    gemm2<<<dim3(N1_ / 128, 1, B_), 256>>>(W2, b2);
    fin_stats2<<<1, O2_>>>(g2, be2);
    transpose_out<<<dim3(N1_ / 32, O2_ / 32, B_), dim3(32, 8)>>>(out);
}